// round 6
// baseline (speedup 1.0000x reference)
#include <cuda_runtime.h>
#include <cuda_bf16.h>
#include <cstdint>

typedef __nv_bfloat16 bf16;

#define BB 4
#define CC 1024
#define CIN 512
#define NT 2048

// ---------------- static scratch ----------------
__device__ __align__(256) bf16 s_xT_h[BB * NT * CC];
__device__ __align__(256) bf16 s_xT_l[BB * NT * CC];
__device__ __align__(256) bf16 s_wg_h[CIN * CC], s_wg_l[CIN * CC];
__device__ __align__(256) bf16 s_wt_h[CIN * CC], s_wt_l[CIN * CC];
__device__ __align__(256) bf16 s_wp_h[CIN * CC], s_wp_l[CIN * CC];
__device__ __align__(256) bf16 s_ww_h[CC * CIN], s_ww_l[CC * CIN];
__device__ __align__(256) bf16 s_th_h[BB * NT * CIN], s_th_l[BB * NT * CIN];
__device__ __align__(256) bf16 s_ph_h[BB * NT * CIN], s_ph_l[BB * NT * CIN];
__device__ __align__(256) bf16 s_gs_h[BB * CIN * NT], s_gs_l[BB * CIN * NT];
__device__ __align__(256) float s_f[BB * NT * NT];
__device__ __align__(256) bf16 s_at_h[BB * NT * NT], s_at_l[BB * NT * NT];
__device__ __align__(256) bf16 s_y_h[BB * NT * CIN], s_y_l[BB * NT * CIN];
__device__ __align__(256) float s_wy[BB * CC * NT];

// ---------------- helpers ----------------
__device__ __forceinline__ uint32_t smem_u32(const void* p) {
    uint32_t a;
    asm("{ .reg .u64 t; cvta.to.shared.u64 t, %1; cvt.u32.u64 %0, t; }" : "=r"(a) : "l"(p));
    return a;
}
__device__ __forceinline__ void st_split2(bf16* hi, bf16* lo, float v0, float v1) {
    bf16 h0 = __float2bfloat16(v0), h1 = __float2bfloat16(v1);
    *(uint32_t*)hi = (uint32_t)__bfloat16_as_ushort(h0) |
                     ((uint32_t)__bfloat16_as_ushort(h1) << 16);
    bf16 l0 = __float2bfloat16(v0 - __bfloat162float(h0));
    bf16 l1 = __float2bfloat16(v1 - __bfloat162float(h1));
    *(uint32_t*)lo = (uint32_t)__bfloat16_as_ushort(l0) |
                     ((uint32_t)__bfloat16_as_ushort(l1) << 16);
}
__device__ __forceinline__ void st_split4(bf16* hi, bf16* lo, float v0, float v1, float v2, float v3) {
    st_split2(hi, lo, v0, v1);
    st_split2(hi + 2, lo + 2, v2, v3);
}

// ---------------- HMMA GEMM ----------------
// D[r,c] = sum_k (Ah+Al)[r,k] * (Bh+Bl)[c,k]  via HH + HL + LH
// CTA tile 128x128, K-chunk 64, 16 warps (4x4), warp tile 32x32, 3-stage cp.async.
#define NSTG 3
#define TILE_B 16384             // one 128x64 bf16 tile
#define STG_BYTES (4 * TILE_B)
#define SMEM_TOTAL (NSTG * STG_BYTES)

__device__ __forceinline__ uint32_t sw_off(int row, int kv) {
    return (uint32_t)(row * 128 + ((kv ^ (row & 7)) << 4));
}

__device__ __forceinline__ void cpa_tile(uint32_t sdst, const bf16* __restrict__ g,
                                         int ld, int k0, int tid) {
#pragma unroll
    for (int i = 0; i < 2; i++) {
        int idx = tid + i * 512;       // 0..1023
        int row = idx >> 3;            // 0..127
        int kv  = idx & 7;
        uint32_t dst = sdst + sw_off(row, kv);
        const void* src = g + (long)row * ld + k0 + kv * 8;
        asm volatile("cp.async.cg.shared.global [%0], [%1], 16;" :: "r"(dst), "l"(src));
    }
}

__device__ __forceinline__ void ldmA(uint32_t* r, uint32_t base, int m0, int k16, int lane) {
    int m = m0 + (lane & 15);
    int kv = k16 * 2 + (lane >> 4);
    uint32_t addr = base + sw_off(m, kv);
    asm volatile("ldmatrix.sync.aligned.m8n8.x4.shared.b16 {%0,%1,%2,%3}, [%4];"
                 : "=r"(r[0]), "=r"(r[1]), "=r"(r[2]), "=r"(r[3]) : "r"(addr));
}
__device__ __forceinline__ void ldmB(uint32_t* r, uint32_t base, int n0, int k16, int lane) {
    int row = n0 + (lane & 7) + ((lane >> 4) << 3);
    int kv = k16 * 2 + ((lane >> 3) & 1);
    uint32_t addr = base + sw_off(row, kv);
    asm volatile("ldmatrix.sync.aligned.m8n8.x4.shared.b16 {%0,%1,%2,%3}, [%4];"
                 : "=r"(r[0]), "=r"(r[1]), "=r"(r[2]), "=r"(r[3]) : "r"(addr));
}
__device__ __forceinline__ void mmaOp(float* c, const uint32_t* a, const uint32_t* b) {
    asm volatile(
        "mma.sync.aligned.m16n8k16.row.col.f32.bf16.bf16.f32 "
        "{%0,%1,%2,%3},{%4,%5,%6,%7},{%8,%9},{%0,%1,%2,%3};"
        : "+f"(c[0]), "+f"(c[1]), "+f"(c[2]), "+f"(c[3])
        : "r"(a[0]), "r"(a[1]), "r"(a[2]), "r"(a[3]), "r"(b[0]), "r"(b[1]));
}

// If bH2 != nullptr, gridDim.z == 2*BB and blocks with z >= BB use the
// alternate B / bias / output set (fused theta+phi launch).
template <int OUT_SPLIT>
__global__ void __launch_bounds__(512, 1)
gemm_tc(const bf16* __restrict__ aH, const bf16* __restrict__ aL, long aS, int lda,
        const bf16* __restrict__ bH, const bf16* __restrict__ bL, long bS, int ldb,
        float* __restrict__ outF, bf16* __restrict__ oH, bf16* __restrict__ oL,
        long oS, int ldc, const float* __restrict__ rBias,
        const float* __restrict__ cBias, int K,
        const bf16* __restrict__ bH2, const bf16* __restrict__ bL2,
        const float* __restrict__ cBias2,
        bf16* __restrict__ oH2, bf16* __restrict__ oL2)
{
    extern __shared__ char smraw[];
    const uint32_t sb = smem_u32(smraw);

    const int tid = threadIdx.x, wid = tid >> 5, lane = tid & 31;
    const int bn = blockIdx.x * 128, bm = blockIdx.y * 128;
    int bz = blockIdx.z;
    if (bH2 && bz >= BB) {
        bz -= BB;
        bH = bH2; bL = bL2; cBias = cBias2; oH = oH2; oL = oL2;
    }
    const int wm = (wid >> 2) * 32;   // 0,32,64,96
    const int wn = (wid & 3) * 32;    // 0,32,64,96

    const bf16* A0 = aH + (long)bz * aS + (long)bm * lda;
    const bf16* A1 = aL + (long)bz * aS + (long)bm * lda;
    const bf16* B0 = bH + (long)bz * bS + (long)bn * ldb;
    const bf16* B1 = bL + (long)bz * bS + (long)bn * ldb;
    const int nch = K >> 6;

    float acc[2][4][4];
#pragma unroll
    for (int i = 0; i < 2; i++)
#pragma unroll
        for (int j = 0; j < 4; j++)
#pragma unroll
            for (int e = 0; e < 4; e++) acc[i][j][e] = 0.f;

#pragma unroll
    for (int s = 0; s < NSTG - 1; s++) {
        uint32_t st = sb + s * STG_BYTES;
        int k0 = s << 6;
        cpa_tile(st,              A0, lda, k0, tid);
        cpa_tile(st + TILE_B,     A1, lda, k0, tid);
        cpa_tile(st + 2 * TILE_B, B0, ldb, k0, tid);
        cpa_tile(st + 3 * TILE_B, B1, ldb, k0, tid);
        asm volatile("cp.async.commit_group;");
    }

    for (int c = 0; c < nch; c++) {
        asm volatile("cp.async.wait_group 1;");
        __syncthreads();
        if (c + NSTG - 1 < nch) {
            uint32_t st = sb + ((c + NSTG - 1) % NSTG) * STG_BYTES;
            int k0 = (c + NSTG - 1) << 6;
            cpa_tile(st,              A0, lda, k0, tid);
            cpa_tile(st + TILE_B,     A1, lda, k0, tid);
            cpa_tile(st + 2 * TILE_B, B0, ldb, k0, tid);
            cpa_tile(st + 3 * TILE_B, B1, ldb, k0, tid);
        }
        asm volatile("cp.async.commit_group;");

        const uint32_t st = sb + (c % NSTG) * STG_BYTES;
#pragma unroll
        for (int k16 = 0; k16 < 4; k16++) {
            uint32_t fAh[2][4], fAl[2][4], fBh[2][4], fBl[2][4];
#pragma unroll
            for (int mt = 0; mt < 2; mt++) {
                ldmA(fAh[mt], st,          wm + mt * 16, k16, lane);
                ldmA(fAl[mt], st + TILE_B, wm + mt * 16, k16, lane);
            }
            ldmB(fBh[0], st + 2 * TILE_B, wn,      k16, lane);
            ldmB(fBh[1], st + 2 * TILE_B, wn + 16, k16, lane);
            ldmB(fBl[0], st + 3 * TILE_B, wn,      k16, lane);
            ldmB(fBl[1], st + 3 * TILE_B, wn + 16, k16, lane);
#pragma unroll
            for (int mt = 0; mt < 2; mt++) {
#pragma unroll
                for (int nt = 0; nt < 4; nt++) {
                    const uint32_t* bh = &fBh[nt >> 1][(nt & 1) * 2];
                    const uint32_t* bl = &fBl[nt >> 1][(nt & 1) * 2];
                    mmaOp(acc[mt][nt], fAh[mt], bh);
                    mmaOp(acc[mt][nt], fAh[mt], bl);
                    mmaOp(acc[mt][nt], fAl[mt], bh);
                }
            }
        }
        __syncthreads();
    }

    // epilogue
    const int rr = lane >> 2;
    const int cc2 = (lane & 3) * 2;
#pragma unroll
    for (int mt = 0; mt < 2; mt++) {
#pragma unroll
        for (int nt = 0; nt < 4; nt++) {
            int row0 = bm + wm + mt * 16 + rr;
            int col = bn + wn + nt * 8 + cc2;
            float cb0 = cBias ? cBias[col] : 0.f;
            float cb1 = cBias ? cBias[col + 1] : 0.f;
#pragma unroll
            for (int h = 0; h < 2; h++) {
                int row = row0 + h * 8;
                float rb = rBias ? rBias[row] : 0.f;
                float v0 = acc[mt][nt][h * 2 + 0] + rb + cb0;
                float v1 = acc[mt][nt][h * 2 + 1] + rb + cb1;
                long o = (long)bz * oS + (long)row * ldc + col;
                if (OUT_SPLIT == 0) {
                    *(float2*)(outF + o) = make_float2(v0, v1);
                } else {
                    st_split2(oH + o, oL + o, v0, v1);
                }
            }
        }
    }
}

// ---------------- elementwise kernels ----------------
__global__ void __launch_bounds__(256) split_w4(
    const float* __restrict__ w0, const float* __restrict__ w1,
    const float* __restrict__ w2, const float* __restrict__ w3,
    bf16* __restrict__ h0, bf16* __restrict__ l0,
    bf16* __restrict__ h1, bf16* __restrict__ l1,
    bf16* __restrict__ h2, bf16* __restrict__ l2,
    bf16* __restrict__ h3, bf16* __restrict__ l3)
{
    const int seg = blockIdx.x >> 11;
    const int i = (blockIdx.x & 2047) * 256 + threadIdx.x;
    const float* w = seg == 0 ? w0 : seg == 1 ? w1 : seg == 2 ? w2 : w3;
    bf16* hi = seg == 0 ? h0 : seg == 1 ? h1 : seg == 2 ? h2 : h3;
    bf16* lo = seg == 0 ? l0 : seg == 1 ? l1 : seg == 2 ? l2 : l3;
    float v = w[i];
    bf16 h = __float2bfloat16(v);
    hi[i] = h;
    lo[i] = __float2bfloat16(v - __bfloat162float(h));
}

__global__ void __launch_bounds__(256) xpose_split(const float* __restrict__ x,
                                                   bf16* __restrict__ hi, bf16* __restrict__ lo)
{
    __shared__ float t[32][33];
    const int b = blockIdx.z, n0 = blockIdx.x * 32, c0 = blockIdx.y * 32;
    const int tx = threadIdx.x & 31, ty = threadIdx.x >> 5;
#pragma unroll
    for (int i = 0; i < 4; i++) {
        int r = ty + i * 8;
        t[r][tx] = x[((long)b * CC + c0 + r) * NT + n0 + tx];
    }
    __syncthreads();
#pragma unroll
    for (int i = 0; i < 4; i++) {
        int r = ty + i * 8;
        float v = t[tx][r];
        long o = ((long)b * NT + n0 + r) * CC + c0 + tx;
        bf16 h = __float2bfloat16(v);
        hi[o] = h;
        lo[o] = __float2bfloat16(v - __bfloat162float(h));
    }
}

__global__ void __launch_bounds__(256) softmax_split(const float* __restrict__ f,
                                                     bf16* __restrict__ hi, bf16* __restrict__ lo)
{
    const float4* pv = (const float4*)(f + (size_t)blockIdx.x * NT);
    const int tid = threadIdx.x;
    float4 a = pv[tid], b = pv[tid + 256];
    float m = fmaxf(fmaxf(fmaxf(a.x, a.y), fmaxf(a.z, a.w)),
                    fmaxf(fmaxf(b.x, b.y), fmaxf(b.z, b.w)));
    __shared__ float red[8];
#pragma unroll
    for (int o = 16; o > 0; o >>= 1) m = fmaxf(m, __shfl_xor_sync(~0u, m, o));
    if ((tid & 31) == 0) red[tid >> 5] = m;
    __syncthreads();
    float mm = red[0];
#pragma unroll
    for (int i = 1; i < 8; i++) mm = fmaxf(mm, red[i]);
    __syncthreads();
    a.x = expf(a.x - mm); a.y = expf(a.y - mm); a.z = expf(a.z - mm); a.w = expf(a.w - mm);
    b.x = expf(b.x - mm); b.y = expf(b.y - mm); b.z = expf(b.z - mm); b.w = expf(b.w - mm);
    float s = (a.x + a.y) + (a.z + a.w) + (b.x + b.y) + (b.z + b.w);
#pragma unroll
    for (int o = 16; o > 0; o >>= 1) s += __shfl_xor_sync(~0u, s, o);
    if ((tid & 31) == 0) red[tid >> 5] = s;
    __syncthreads();
    float sum = 0.f;
#pragma unroll
    for (int i = 0; i < 8; i++) sum += red[i];
    float inv = 1.0f / sum;
    size_t off = (size_t)blockIdx.x * NT;
    st_split4(hi + off + tid * 4, lo + off + tid * 4,
              a.x * inv, a.y * inv, a.z * inv, a.w * inv);
    st_split4(hi + off + 1024 + tid * 4, lo + off + 1024 + tid * 4,
              b.x * inv, b.y * inv, b.z * inv, b.w * inv);
}

__global__ void __launch_bounds__(256)
bn_residual(const float* __restrict__ wy, const float* __restrict__ x,
            const float* __restrict__ gamma, const float* __restrict__ beta,
            float* __restrict__ out)
{
    const int c = blockIdx.x, tid = threadIdx.x;
    float vals[32], s = 0.f, ss = 0.f;
#pragma unroll
    for (int b = 0; b < BB; b++) {
        const float* p = wy + ((size_t)b * CC + c) * NT;
#pragma unroll
        for (int j = 0; j < 8; j++) {
            float v = p[tid + j * 256];
            vals[b * 8 + j] = v; s += v; ss += v * v;
        }
    }
    __shared__ float r1[8], r2[8];
#pragma unroll
    for (int o = 16; o > 0; o >>= 1) {
        s += __shfl_xor_sync(~0u, s, o);
        ss += __shfl_xor_sync(~0u, ss, o);
    }
    if ((tid & 31) == 0) { r1[tid >> 5] = s; r2[tid >> 5] = ss; }
    __syncthreads();
    s = 0.f; ss = 0.f;
#pragma unroll
    for (int i = 0; i < 8; i++) { s += r1[i]; ss += r2[i]; }
    const float cnt = (float)(BB * NT);
    float mean = s / cnt;
    float var = ss / cnt - mean * mean;
    float scale = rsqrtf(var + 1e-5f) * gamma[c];
    float shift = beta[c] - mean * scale;
#pragma unroll
    for (int b = 0; b < BB; b++) {
        size_t off = ((size_t)b * CC + c) * NT;
#pragma unroll
        for (int j = 0; j < 8; j++) {
            int n = tid + j * 256;
            out[off + n] = vals[b * 8 + j] * scale + shift + x[off + n];
        }
    }
}

// ---------------------------------------------------------------------------
extern "C" void kernel_launch(void* const* d_in, const int* in_sizes, int n_in,
                              void* d_out, int out_size)
{
    const float* x   = (const float*)d_in[0];
    const float* gw  = (const float*)d_in[1];
    const float* gb  = (const float*)d_in[2];
    const float* tw  = (const float*)d_in[3];
    const float* tb  = (const float*)d_in[4];
    const float* pw  = (const float*)d_in[5];
    const float* pb  = (const float*)d_in[6];
    const float* ww  = (const float*)d_in[7];
    const float* wb  = (const float*)d_in[8];
    const float* bg  = (const float*)d_in[9];
    const float* bbt = (const float*)d_in[10];
    float* out = (float*)d_out;

    bf16 *xTh, *xTl, *wgh, *wgl, *wth, *wtl, *wph, *wpl, *wwh, *wwl;
    bf16 *thh, *thl, *phh, *phl, *gsh, *gsl, *ath, *atl, *yh, *yl;
    float *ff, *wy;
    cudaGetSymbolAddress((void**)&xTh, s_xT_h); cudaGetSymbolAddress((void**)&xTl, s_xT_l);
    cudaGetSymbolAddress((void**)&wgh, s_wg_h); cudaGetSymbolAddress((void**)&wgl, s_wg_l);
    cudaGetSymbolAddress((void**)&wth, s_wt_h); cudaGetSymbolAddress((void**)&wtl, s_wt_l);
    cudaGetSymbolAddress((void**)&wph, s_wp_h); cudaGetSymbolAddress((void**)&wpl, s_wp_l);
    cudaGetSymbolAddress((void**)&wwh, s_ww_h); cudaGetSymbolAddress((void**)&wwl, s_ww_l);
    cudaGetSymbolAddress((void**)&thh, s_th_h); cudaGetSymbolAddress((void**)&thl, s_th_l);
    cudaGetSymbolAddress((void**)&phh, s_ph_h); cudaGetSymbolAddress((void**)&phl, s_ph_l);
    cudaGetSymbolAddress((void**)&gsh, s_gs_h); cudaGetSymbolAddress((void**)&gsl, s_gs_l);
    cudaGetSymbolAddress((void**)&ath, s_at_h); cudaGetSymbolAddress((void**)&atl, s_at_l);
    cudaGetSymbolAddress((void**)&yh,  s_y_h);  cudaGetSymbolAddress((void**)&yl,  s_y_l);
    cudaGetSymbolAddress((void**)&ff,  s_f);    cudaGetSymbolAddress((void**)&wy,  s_wy);

    cudaFuncSetAttribute(gemm_tc<0>, cudaFuncAttributeMaxDynamicSharedMemorySize, SMEM_TOTAL);
    cudaFuncSetAttribute(gemm_tc<1>, cudaFuncAttributeMaxDynamicSharedMemorySize, SMEM_TOTAL);

    split_w4<<<4 * 2048, 256>>>(gw, tw, pw, ww,
                                wgh, wgl, wth, wtl, wph, wpl, wwh, wwl);
    xpose_split<<<dim3(NT / 32, CC / 32, BB), 256>>>(x, xTh, xTl);

    const long sXT = (long)NT * CC, sPR = (long)NT * CIN;
    const long sGS = (long)CIN * NT, sAT = (long)NT * NT, sWY = (long)CC * NT;

    // theta + phi fused (rows=NT, cols=CIN, K=CC; z in [0,8))
    gemm_tc<1><<<dim3(CIN / 128, NT / 128, 2 * BB), 512, SMEM_TOTAL>>>(
        xTh, xTl, sXT, CC, wth, wtl, 0, CC, nullptr, thh, thl, sPR, CIN, nullptr, tb, CC,
        wph, wpl, pb, phh, phl);
    // g_s[b,o,m] (rows=CIN, cols=NT, K=CC)
    gemm_tc<1><<<dim3(NT / 128, CIN / 128, BB), 512, SMEM_TOTAL>>>(
        wgh, wgl, 0, CC, xTh, xTl, sXT, CC, nullptr, gsh, gsl, sGS, NT, gb, nullptr, CC,
        nullptr, nullptr, nullptr, nullptr, nullptr);
    // f[b,n,m] (rows=NT, cols=NT, K=CIN)
    gemm_tc<0><<<dim3(NT / 128, NT / 128, BB), 512, SMEM_TOTAL>>>(
        thh, thl, sPR, CIN, phh, phl, sPR, CIN, ff, nullptr, nullptr, sAT, NT, nullptr, nullptr, CIN,
        nullptr, nullptr, nullptr, nullptr, nullptr);
    // softmax -> split attn
    softmax_split<<<BB * NT, 256>>>(ff, ath, atl);
    // y[b,n,o] (rows=NT, cols=CIN, K=NT)
    gemm_tc<1><<<dim3(CIN / 128, NT / 128, BB), 512, SMEM_TOTAL>>>(
        ath, atl, sAT, NT, gsh, gsl, sGS, NT, nullptr, yh, yl, sPR, CIN, nullptr, nullptr, NT,
        nullptr, nullptr, nullptr, nullptr, nullptr);
    // w_y[b,c,n] (rows=CC, cols=NT, K=CIN)
    gemm_tc<0><<<dim3(NT / 128, CC / 128, BB), 512, SMEM_TOTAL>>>(
        wwh, wwl, 0, CIN, yh, yl, sPR, CIN, wy, nullptr, nullptr, sWY, NT, wb, nullptr, CIN,
        nullptr, nullptr, nullptr, nullptr, nullptr);
    // BN + residual
    bn_residual<<<CC, 256>>>(wy, x, bg, bbt, out);
}

// round 7
// speedup vs baseline: 1.0001x; 1.0001x over previous
#include <cuda_runtime.h>
#include <cuda_bf16.h>
#include <cstdint>

typedef __nv_bfloat16 bf16;

#define BB 4
#define CC 1024
#define CIN 512
#define NT 2048

// ---------------- static scratch ----------------
__device__ __align__(256) bf16 s_xT_h[BB * NT * CC];
__device__ __align__(256) bf16 s_xT_l[BB * NT * CC];
__device__ __align__(256) bf16 s_wg_h[CIN * CC], s_wg_l[CIN * CC];
__device__ __align__(256) bf16 s_wt_h[CIN * CC], s_wt_l[CIN * CC];
__device__ __align__(256) bf16 s_wp_h[CIN * CC], s_wp_l[CIN * CC];
__device__ __align__(256) bf16 s_ww_h[CC * CIN], s_ww_l[CC * CIN];
__device__ __align__(256) bf16 s_th_h[BB * NT * CIN], s_th_l[BB * NT * CIN];
__device__ __align__(256) bf16 s_ph_h[BB * NT * CIN], s_ph_l[BB * NT * CIN];
__device__ __align__(256) bf16 s_gs_h[BB * CIN * NT], s_gs_l[BB * CIN * NT];
__device__ __align__(256) float s_f[BB * NT * NT];
__device__ __align__(256) bf16 s_at_h[BB * NT * NT], s_at_l[BB * NT * NT];
__device__ __align__(256) bf16 s_y_h[BB * NT * CIN], s_y_l[BB * NT * CIN];
__device__ __align__(256) float s_wy[BB * CC * NT];

// ---------------- helpers ----------------
__device__ __forceinline__ uint32_t smem_u32(const void* p) {
    uint32_t a;
    asm("{ .reg .u64 t; cvta.to.shared.u64 t, %1; cvt.u32.u64 %0, t; }" : "=r"(a) : "l"(p));
    return a;
}
__device__ __forceinline__ void st_split2(bf16* hi, bf16* lo, float v0, float v1) {
    bf16 h0 = __float2bfloat16(v0), h1 = __float2bfloat16(v1);
    *(uint32_t*)hi = (uint32_t)__bfloat16_as_ushort(h0) |
                     ((uint32_t)__bfloat16_as_ushort(h1) << 16);
    bf16 l0 = __float2bfloat16(v0 - __bfloat162float(h0));
    bf16 l1 = __float2bfloat16(v1 - __bfloat162float(h1));
    *(uint32_t*)lo = (uint32_t)__bfloat16_as_ushort(l0) |
                     ((uint32_t)__bfloat16_as_ushort(l1) << 16);
}
__device__ __forceinline__ void st_split4(bf16* hi, bf16* lo, float v0, float v1, float v2, float v3) {
    st_split2(hi, lo, v0, v1);
    st_split2(hi + 2, lo + 2, v2, v3);
}

// ---------------- HMMA GEMM ----------------
// D[r,c] = sum_k (Ah+Al)[r,k] * (Bh+Bl)[c,k]  via HH + HL + LH
// CTA tile 128x128, K-chunk 64, 16 warps (4x4), warp tile 32x32, 3-stage cp.async.
// MMAs issued product-major so same-acc dependents are 8 issue slots apart.
#define NSTG 3
#define TILE_B 16384
#define STG_BYTES (4 * TILE_B)
#define SMEM_TOTAL (NSTG * STG_BYTES)

__device__ __forceinline__ uint32_t sw_off(int row, int kv) {
    return (uint32_t)(row * 128 + ((kv ^ (row & 7)) << 4));
}

__device__ __forceinline__ void cpa_tile(uint32_t sdst, const bf16* __restrict__ g,
                                         int ld, int k0, int tid) {
#pragma unroll
    for (int i = 0; i < 2; i++) {
        int idx = tid + i * 512;
        int row = idx >> 3;
        int kv  = idx & 7;
        uint32_t dst = sdst + sw_off(row, kv);
        const void* src = g + (long)row * ld + k0 + kv * 8;
        asm volatile("cp.async.cg.shared.global [%0], [%1], 16;" :: "r"(dst), "l"(src));
    }
}

__device__ __forceinline__ void ldmA(uint32_t* r, uint32_t base, int m0, int k16, int lane) {
    int m = m0 + (lane & 15);
    int kv = k16 * 2 + (lane >> 4);
    uint32_t addr = base + sw_off(m, kv);
    asm volatile("ldmatrix.sync.aligned.m8n8.x4.shared.b16 {%0,%1,%2,%3}, [%4];"
                 : "=r"(r[0]), "=r"(r[1]), "=r"(r[2]), "=r"(r[3]) : "r"(addr));
}
__device__ __forceinline__ void ldmB(uint32_t* r, uint32_t base, int n0, int k16, int lane) {
    int row = n0 + (lane & 7) + ((lane >> 4) << 3);
    int kv = k16 * 2 + ((lane >> 3) & 1);
    uint32_t addr = base + sw_off(row, kv);
    asm volatile("ldmatrix.sync.aligned.m8n8.x4.shared.b16 {%0,%1,%2,%3}, [%4];"
                 : "=r"(r[0]), "=r"(r[1]), "=r"(r[2]), "=r"(r[3]) : "r"(addr));
}
__device__ __forceinline__ void mmaOp(float* c, const uint32_t* a, const uint32_t* b) {
    asm volatile(
        "mma.sync.aligned.m16n8k16.row.col.f32.bf16.bf16.f32 "
        "{%0,%1,%2,%3},{%4,%5,%6,%7},{%8,%9},{%0,%1,%2,%3};"
        : "+f"(c[0]), "+f"(c[1]), "+f"(c[2]), "+f"(c[3])
        : "r"(a[0]), "r"(a[1]), "r"(a[2]), "r"(a[3]), "r"(b[0]), "r"(b[1]));
}

template <int OUT_SPLIT>
__global__ void __launch_bounds__(512, 1)
gemm_tc(const bf16* __restrict__ aH, const bf16* __restrict__ aL, long aS, int lda,
        const bf16* __restrict__ bH, const bf16* __restrict__ bL, long bS, int ldb,
        float* __restrict__ outF, bf16* __restrict__ oH, bf16* __restrict__ oL,
        long oS, int ldc, const float* __restrict__ rBias,
        const float* __restrict__ cBias, int K,
        const bf16* __restrict__ bH2, const bf16* __restrict__ bL2,
        const float* __restrict__ cBias2,
        bf16* __restrict__ oH2, bf16* __restrict__ oL2)
{
    extern __shared__ char smraw[];
    const uint32_t sb = smem_u32(smraw);

    const int tid = threadIdx.x, wid = tid >> 5, lane = tid & 31;
    const int bn = blockIdx.x * 128, bm = blockIdx.y * 128;
    int bz = blockIdx.z;
    if (bH2 && bz >= BB) {
        bz -= BB;
        bH = bH2; bL = bL2; cBias = cBias2; oH = oH2; oL = oL2;
    }
    const int wm = (wid >> 2) * 32;
    const int wn = (wid & 3) * 32;

    const bf16* A0 = aH + (long)bz * aS + (long)bm * lda;
    const bf16* A1 = aL + (long)bz * aS + (long)bm * lda;
    const bf16* B0 = bH + (long)bz * bS + (long)bn * ldb;
    const bf16* B1 = bL + (long)bz * bS + (long)bn * ldb;
    const int nch = K >> 6;

    float acc[2][4][4];
#pragma unroll
    for (int i = 0; i < 2; i++)
#pragma unroll
        for (int j = 0; j < 4; j++)
#pragma unroll
            for (int e = 0; e < 4; e++) acc[i][j][e] = 0.f;

#pragma unroll
    for (int s = 0; s < NSTG - 1; s++) {
        uint32_t st = sb + s * STG_BYTES;
        int k0 = s << 6;
        cpa_tile(st,              A0, lda, k0, tid);
        cpa_tile(st + TILE_B,     A1, lda, k0, tid);
        cpa_tile(st + 2 * TILE_B, B0, ldb, k0, tid);
        cpa_tile(st + 3 * TILE_B, B1, ldb, k0, tid);
        asm volatile("cp.async.commit_group;");
    }

    for (int c = 0; c < nch; c++) {
        asm volatile("cp.async.wait_group 1;");
        __syncthreads();
        if (c + NSTG - 1 < nch) {
            uint32_t st = sb + ((c + NSTG - 1) % NSTG) * STG_BYTES;
            int k0 = (c + NSTG - 1) << 6;
            cpa_tile(st,              A0, lda, k0, tid);
            cpa_tile(st + TILE_B,     A1, lda, k0, tid);
            cpa_tile(st + 2 * TILE_B, B0, ldb, k0, tid);
            cpa_tile(st + 3 * TILE_B, B1, ldb, k0, tid);
        }
        asm volatile("cp.async.commit_group;");

        const uint32_t st = sb + (c % NSTG) * STG_BYTES;
#pragma unroll
        for (int k16 = 0; k16 < 4; k16++) {
            uint32_t fAh[2][4], fAl[2][4], fBh[2][4], fBl[2][4];
#pragma unroll
            for (int mt = 0; mt < 2; mt++) {
                ldmA(fAh[mt], st,          wm + mt * 16, k16, lane);
                ldmA(fAl[mt], st + TILE_B, wm + mt * 16, k16, lane);
            }
            ldmB(fBh[0], st + 2 * TILE_B, wn,      k16, lane);
            ldmB(fBh[1], st + 2 * TILE_B, wn + 16, k16, lane);
            ldmB(fBl[0], st + 3 * TILE_B, wn,      k16, lane);
            ldmB(fBl[1], st + 3 * TILE_B, wn + 16, k16, lane);
            // product-major issue: all HH, then all HL, then all LH —
            // dependent MMAs on the same acc are 8 issue slots apart.
#pragma unroll
            for (int mt = 0; mt < 2; mt++)
#pragma unroll
                for (int nt = 0; nt < 4; nt++)
                    mmaOp(acc[mt][nt], fAh[mt], &fBh[nt >> 1][(nt & 1) * 2]);
#pragma unroll
            for (int mt = 0; mt < 2; mt++)
#pragma unroll
                for (int nt = 0; nt < 4; nt++)
                    mmaOp(acc[mt][nt], fAh[mt], &fBl[nt >> 1][(nt & 1) * 2]);
#pragma unroll
            for (int mt = 0; mt < 2; mt++)
#pragma unroll
                for (int nt = 0; nt < 4; nt++)
                    mmaOp(acc[mt][nt], fAl[mt], &fBh[nt >> 1][(nt & 1) * 2]);
        }
        __syncthreads();
    }

    // epilogue
    const int rr = lane >> 2;
    const int cc2 = (lane & 3) * 2;
#pragma unroll
    for (int mt = 0; mt < 2; mt++) {
#pragma unroll
        for (int nt = 0; nt < 4; nt++) {
            int row0 = bm + wm + mt * 16 + rr;
            int col = bn + wn + nt * 8 + cc2;
            float cb0 = cBias ? cBias[col] : 0.f;
            float cb1 = cBias ? cBias[col + 1] : 0.f;
#pragma unroll
            for (int h = 0; h < 2; h++) {
                int row = row0 + h * 8;
                float rb = rBias ? rBias[row] : 0.f;
                float v0 = acc[mt][nt][h * 2 + 0] + rb + cb0;
                float v1 = acc[mt][nt][h * 2 + 1] + rb + cb1;
                long o = (long)bz * oS + (long)row * ldc + col;
                if (OUT_SPLIT == 0) {
                    *(float2*)(outF + o) = make_float2(v0, v1);
                } else {
                    st_split2(oH + o, oL + o, v0, v1);
                }
            }
        }
    }
}

// ---------------- elementwise kernels ----------------
__global__ void __launch_bounds__(256) split_w4(
    const float* __restrict__ w0, const float* __restrict__ w1,
    const float* __restrict__ w2, const float* __restrict__ w3,
    bf16* __restrict__ h0, bf16* __restrict__ l0,
    bf16* __restrict__ h1, bf16* __restrict__ l1,
    bf16* __restrict__ h2, bf16* __restrict__ l2,
    bf16* __restrict__ h3, bf16* __restrict__ l3)
{
    const int seg = blockIdx.x >> 11;
    const int i = (blockIdx.x & 2047) * 256 + threadIdx.x;
    const float* w = seg == 0 ? w0 : seg == 1 ? w1 : seg == 2 ? w2 : w3;
    bf16* hi = seg == 0 ? h0 : seg == 1 ? h1 : seg == 2 ? h2 : h3;
    bf16* lo = seg == 0 ? l0 : seg == 1 ? l1 : seg == 2 ? l2 : l3;
    float v = w[i];
    bf16 h = __float2bfloat16(v);
    hi[i] = h;
    lo[i] = __float2bfloat16(v - __bfloat162float(h));
}

__global__ void __launch_bounds__(256) xpose_split(const float* __restrict__ x,
                                                   bf16* __restrict__ hi, bf16* __restrict__ lo)
{
    __shared__ float t[32][33];
    const int b = blockIdx.z, n0 = blockIdx.x * 32, c0 = blockIdx.y * 32;
    const int tx = threadIdx.x & 31, ty = threadIdx.x >> 5;
#pragma unroll
    for (int i = 0; i < 4; i++) {
        int r = ty + i * 8;
        t[r][tx] = x[((long)b * CC + c0 + r) * NT + n0 + tx];
    }
    __syncthreads();
#pragma unroll
    for (int i = 0; i < 4; i++) {
        int r = ty + i * 8;
        float v = t[tx][r];
        long o = ((long)b * NT + n0 + r) * CC + c0 + tx;
        bf16 h = __float2bfloat16(v);
        hi[o] = h;
        lo[o] = __float2bfloat16(v - __bfloat162float(h));
    }
}

__global__ void __launch_bounds__(256) softmax_split(const float* __restrict__ f,
                                                     bf16* __restrict__ hi, bf16* __restrict__ lo)
{
    const float4* pv = (const float4*)(f + (size_t)blockIdx.x * NT);
    const int tid = threadIdx.x;
    float4 a = pv[tid], b = pv[tid + 256];
    float m = fmaxf(fmaxf(fmaxf(a.x, a.y), fmaxf(a.z, a.w)),
                    fmaxf(fmaxf(b.x, b.y), fmaxf(b.z, b.w)));
    __shared__ float red[8];
#pragma unroll
    for (int o = 16; o > 0; o >>= 1) m = fmaxf(m, __shfl_xor_sync(~0u, m, o));
    if ((tid & 31) == 0) red[tid >> 5] = m;
    __syncthreads();
    float mm = red[0];
#pragma unroll
    for (int i = 1; i < 8; i++) mm = fmaxf(mm, red[i]);
    __syncthreads();
    a.x = expf(a.x - mm); a.y = expf(a.y - mm); a.z = expf(a.z - mm); a.w = expf(a.w - mm);
    b.x = expf(b.x - mm); b.y = expf(b.y - mm); b.z = expf(b.z - mm); b.w = expf(b.w - mm);
    float s = (a.x + a.y) + (a.z + a.w) + (b.x + b.y) + (b.z + b.w);
#pragma unroll
    for (int o = 16; o > 0; o >>= 1) s += __shfl_xor_sync(~0u, s, o);
    if ((tid & 31) == 0) red[tid >> 5] = s;
    __syncthreads();
    float sum = 0.f;
#pragma unroll
    for (int i = 0; i < 8; i++) sum += red[i];
    float inv = 1.0f / sum;
    size_t off = (size_t)blockIdx.x * NT;
    st_split4(hi + off + tid * 4, lo + off + tid * 4,
              a.x * inv, a.y * inv, a.z * inv, a.w * inv);
    st_split4(hi + off + 1024 + tid * 4, lo + off + 1024 + tid * 4,
              b.x * inv, b.y * inv, b.z * inv, b.w * inv);
}

__global__ void __launch_bounds__(256)
bn_residual(const float* __restrict__ wy, const float* __restrict__ x,
            const float* __restrict__ gamma, const float* __restrict__ beta,
            float* __restrict__ out)
{
    const int c = blockIdx.x, tid = threadIdx.x;
    float vals[32], s = 0.f, ss = 0.f;
#pragma unroll
    for (int b = 0; b < BB; b++) {
        const float* p = wy + ((size_t)b * CC + c) * NT;
#pragma unroll
        for (int j = 0; j < 8; j++) {
            float v = p[tid + j * 256];
            vals[b * 8 + j] = v; s += v; ss += v * v;
        }
    }
    __shared__ float r1[8], r2[8];
#pragma unroll
    for (int o = 16; o > 0; o >>= 1) {
        s += __shfl_xor_sync(~0u, s, o);
        ss += __shfl_xor_sync(~0u, ss, o);
    }
    if ((tid & 31) == 0) { r1[tid >> 5] = s; r2[tid >> 5] = ss; }
    __syncthreads();
    s = 0.f; ss = 0.f;
#pragma unroll
    for (int i = 0; i < 8; i++) { s += r1[i]; ss += r2[i]; }
    const float cnt = (float)(BB * NT);
    float mean = s / cnt;
    float var = ss / cnt - mean * mean;
    float scale = rsqrtf(var + 1e-5f) * gamma[c];
    float shift = beta[c] - mean * scale;
#pragma unroll
    for (int b = 0; b < BB; b++) {
        size_t off = ((size_t)b * CC + c) * NT;
#pragma unroll
        for (int j = 0; j < 8; j++) {
            int n = tid + j * 256;
            out[off + n] = vals[b * 8 + j] * scale + shift + x[off + n];
        }
    }
}

// ---------------------------------------------------------------------------
extern "C" void kernel_launch(void* const* d_in, const int* in_sizes, int n_in,
                              void* d_out, int out_size)
{
    const float* x   = (const float*)d_in[0];
    const float* gw  = (const float*)d_in[1];
    const float* gb  = (const float*)d_in[2];
    const float* tw  = (const float*)d_in[3];
    const float* tb  = (const float*)d_in[4];
    const float* pw  = (const float*)d_in[5];
    const float* pb  = (const float*)d_in[6];
    const float* ww  = (const float*)d_in[7];
    const float* wb  = (const float*)d_in[8];
    const float* bg  = (const float*)d_in[9];
    const float* bbt = (const float*)d_in[10];
    float* out = (float*)d_out;

    bf16 *xTh, *xTl, *wgh, *wgl, *wth, *wtl, *wph, *wpl, *wwh, *wwl;
    bf16 *thh, *thl, *phh, *phl, *gsh, *gsl, *ath, *atl, *yh, *yl;
    float *ff, *wy;
    cudaGetSymbolAddress((void**)&xTh, s_xT_h); cudaGetSymbolAddress((void**)&xTl, s_xT_l);
    cudaGetSymbolAddress((void**)&wgh, s_wg_h); cudaGetSymbolAddress((void**)&wgl, s_wg_l);
    cudaGetSymbolAddress((void**)&wth, s_wt_h); cudaGetSymbolAddress((void**)&wtl, s_wt_l);
    cudaGetSymbolAddress((void**)&wph, s_wp_h); cudaGetSymbolAddress((void**)&wpl, s_wp_l);
    cudaGetSymbolAddress((void**)&wwh, s_ww_h); cudaGetSymbolAddress((void**)&wwl, s_ww_l);
    cudaGetSymbolAddress((void**)&thh, s_th_h); cudaGetSymbolAddress((void**)&thl, s_th_l);
    cudaGetSymbolAddress((void**)&phh, s_ph_h); cudaGetSymbolAddress((void**)&phl, s_ph_l);
    cudaGetSymbolAddress((void**)&gsh, s_gs_h); cudaGetSymbolAddress((void**)&gsl, s_gs_l);
    cudaGetSymbolAddress((void**)&ath, s_at_h); cudaGetSymbolAddress((void**)&atl, s_at_l);
    cudaGetSymbolAddress((void**)&yh,  s_y_h);  cudaGetSymbolAddress((void**)&yl,  s_y_l);
    cudaGetSymbolAddress((void**)&ff,  s_f);    cudaGetSymbolAddress((void**)&wy,  s_wy);

    cudaFuncSetAttribute(gemm_tc<0>, cudaFuncAttributeMaxDynamicSharedMemorySize, SMEM_TOTAL);
    cudaFuncSetAttribute(gemm_tc<1>, cudaFuncAttributeMaxDynamicSharedMemorySize, SMEM_TOTAL);

    split_w4<<<4 * 2048, 256>>>(gw, tw, pw, ww,
                                wgh, wgl, wth, wtl, wph, wpl, wwh, wwl);
    xpose_split<<<dim3(NT / 32, CC / 32, BB), 256>>>(x, xTh, xTl);

    const long sXT = (long)NT * CC, sPR = (long)NT * CIN;
    const long sGS = (long)CIN * NT, sAT = (long)NT * NT, sWY = (long)CC * NT;

    // theta + phi fused (rows=NT, cols=CIN, K=CC; z in [0,8))
    gemm_tc<1><<<dim3(CIN / 128, NT / 128, 2 * BB), 512, SMEM_TOTAL>>>(
        xTh, xTl, sXT, CC, wth, wtl, 0, CC, nullptr, thh, thl, sPR, CIN, nullptr, tb, CC,
        wph, wpl, pb, phh, phl);
    // g_s[b,o,m] (rows=CIN, cols=NT, K=CC)
    gemm_tc<1><<<dim3(NT / 128, CIN / 128, BB), 512, SMEM_TOTAL>>>(
        wgh, wgl, 0, CC, xTh, xTl, sXT, CC, nullptr, gsh, gsl, sGS, NT, gb, nullptr, CC,
        nullptr, nullptr, nullptr, nullptr, nullptr);
    // f[b,n,m] (rows=NT, cols=NT, K=CIN)
    gemm_tc<0><<<dim3(NT / 128, NT / 128, BB), 512, SMEM_TOTAL>>>(
        thh, thl, sPR, CIN, phh, phl, sPR, CIN, ff, nullptr, nullptr, sAT, NT, nullptr, nullptr, CIN,
        nullptr, nullptr, nullptr, nullptr, nullptr);
    // softmax -> split attn
    softmax_split<<<BB * NT, 256>>>(ff, ath, atl);
    // y[b,n,o] (rows=NT, cols=CIN, K=NT)
    gemm_tc<1><<<dim3(CIN / 128, NT / 128, BB), 512, SMEM_TOTAL>>>(
        ath, atl, sAT, NT, gsh, gsl, sGS, NT, nullptr, yh, yl, sPR, CIN, nullptr, nullptr, NT,
        nullptr, nullptr, nullptr, nullptr, nullptr);
    // w_y[b,c,n] (rows=CC, cols=NT, K=CIN)
    gemm_tc<0><<<dim3(NT / 128, CC / 128, BB), 512, SMEM_TOTAL>>>(
        wwh, wwl, 0, CIN, yh, yl, sPR, CIN, wy, nullptr, nullptr, sWY, NT, wb, nullptr, CIN,
        nullptr, nullptr, nullptr, nullptr, nullptr);
    // BN + residual
    bn_residual<<<CC, 256>>>(wy, x, bg, bbt, out);
}